// round 16
// baseline (speedup 1.0000x reference)
#include <cuda_runtime.h>
#include <cuda_fp16.h>

// Morphological dilation2d, K=7, PAD=3 (zero padding = nn.Unfold), then ReLU.
// out[b,c,h,w] = max(0, max_{i,j}( xp[b,c,h+i,w+j] + weight[c,i,j] ))
// Packed fp16x2 (HADD2 + HMNMX2); ReLU folded into acc init (=0).
//
// R15 + single-barrier restructure: only the halo is zeroed (disjoint from the
// fill region), so zero / weight-load / fill all run concurrently before ONE
// __syncthreads. Fill LDGs issue from cycle 0 -> DRAM latency overlapped.
// Grid 6144, 7 CTAs/SM (5.93 waves). Quad-paired weight table (LDS.128 serves
// 2 taps x 2 kernel rows).
//
// x:      (16, 96, 128, 128) fp32 -> d_in[0]
// weight: (96, 7, 7)         fp32 -> d_in[1]
// out:    fp32

#define HH    128
#define WW    128
#define CC    96
#define BB    16
#define RPC   32            // output rows per CTA
#define SR    38            // smem rows = RPC + 6
#define SROWH 136           // smem row stride in HALVES (272B)
#define NT    256

__device__ __forceinline__ __half2 u2h(unsigned u) { return *reinterpret_cast<__half2*>(&u); }

__global__ __launch_bounds__(NT, 7)
void morph7x7_h2_kernel(const float* __restrict__ x,
                        const float* __restrict__ wt,
                        float* __restrict__ out) {
    __shared__ __half xs[SR * SROWH];
    __shared__ uint4  wq[32];               // [s=0..7][q=0..3] quad-paired weights

    const int bid   = blockIdx.x;
    const int rtile = bid & 3;
    const int plane = bid >> 2;             // b*CC + c
    const int c     = plane % CC;
    const int R0    = rtile * RPC;

    const float* gx = x + (size_t)plane * (HH * WW);
    const int tid = threadIdx.x;

    // Fill region: smem rows [g0+3-R0, g1+3-R0), half-cols [4,132).
    const int g0 = (R0 - 3 > 0) ? R0 - 3 : 0;
    const int g1 = (R0 + 35 < HH) ? R0 + 35 : HH;
    const int sr0 = g0 + 3 - R0;            // first filled smem row (0 or 3)
    const int sr1 = g1 + 3 - R0;            // one past last filled smem row (35 or 38)

    // ---- zero halo ONLY (disjoint from fill region) -> no barrier needed between ----
    // Side halo: half-cols 0-3 and 132-135 of every row (uint2 each).
    if (tid < 76) {
        const int row  = tid >> 1;
        const int side = tid & 1;
        *reinterpret_cast<uint2*>(&xs[row * SROWH + side * 132]) = make_uint2(0u, 0u);
    }
    // Top/bottom stripes (middle half-cols 4..131 as 32 uint2 per row), rows
    // outside [sr0, sr1). At most 3 rows (edge tiles only).
    if (tid >= 76 && tid < 172) {
        const int k  = tid - 76;
        const int rr = k >> 5;               // 0..2
        const int cc = k & 31;               // 0..31
        const int row = (sr0 > 0) ? rr : (sr1 + rr);   // rtile0: rows 0-2; rtile3: 35-37
        if (row < SR && (row < sr0 || row >= sr1))
            *reinterpret_cast<uint2*>(&xs[row * SROWH + 4 + cc * 4]) = make_uint2(0u, 0u);
    }
    // ---- quad-paired weight table ----
    // wq[s*4+q] = (w2[s][2q], w2[s-1][2q], w2[s][2q+1], w2[s-1][2q+1]);
    // out-of-range slots are 0 (never read by the guarded loop).
    if (tid >= 172 && tid < 204) {
        const int k = tid - 172;
        const int s = k >> 2, q = k & 3;
        const int j0 = 2 * q, j1 = 2 * q + 1;
        unsigned e[4] = {0u, 0u, 0u, 0u};
        if (s < 7) {
            __half2 h2 = __half2half2(__float2half_rn(wt[c * 49 + s * 7 + j0]));
            e[0] = *reinterpret_cast<unsigned*>(&h2);
            if (j1 < 7) {
                __half2 g2 = __half2half2(__float2half_rn(wt[c * 49 + s * 7 + j1]));
                e[2] = *reinterpret_cast<unsigned*>(&g2);
            }
        }
        if (s > 0) {
            __half2 h2 = __half2half2(__float2half_rn(wt[c * 49 + (s - 1) * 7 + j0]));
            e[1] = *reinterpret_cast<unsigned*>(&h2);
            if (j1 < 7) {
                __half2 g2 = __half2half2(__float2half_rn(wt[c * 49 + (s - 1) * 7 + j1]));
                e[3] = *reinterpret_cast<unsigned*>(&g2);
            }
        }
        wq[k] = make_uint4(e[0], e[1], e[2], e[3]);
    }

    // ---- fill interior rows [g0,g1), fp32 -> fp16, data at half-col 4 ----
    // Runs concurrently with the halo zeroing above (disjoint addresses).
    const int n4 = (g1 - g0) * 32;          // float4 count
    for (int idx = tid; idx < n4; idx += NT) {
        const int rr = idx >> 5;
        const int c4 = idx & 31;
        const int g  = g0 + rr;
        float4 v = reinterpret_cast<const float4*>(gx + g * WW)[c4];
        __half2 p0 = __floats2half2_rn(v.x, v.y);
        __half2 p1 = __floats2half2_rn(v.z, v.w);
        __half2* dst = reinterpret_cast<__half2*>(&xs[(g + 3 - R0) * SROWH + 4 + c4 * 4]);
        dst[0] = p0;
        dst[1] = p1;
    }
    __syncthreads();                        // the ONLY barrier

    // ---- compute: thread = 8 cols x 2 rows ----
    const int tx    = tid & 15;
    const int ty    = tid >> 4;
    const int cbase = tx * 8;               // output col base; LDS.128-aligned reads
    const int r0    = ty * 2;

    // S[0..3]=0 pad; taps for output col w are S[w+1 .. w+7].
    const uint4* rb = reinterpret_cast<const uint4*>(&xs[r0 * SROWH + cbase]);

    __half2 acc0[4], acc1[4];
    const __half2 h2z = __float2half2_rn(0.0f);
    #pragma unroll
    for (int p = 0; p < 4; ++p) { acc0[p] = h2z; acc1[p] = h2z; }   // folds ReLU

    #pragma unroll
    for (int s = 0; s < 8; ++s) {
        const uint4 A = rb[s * 17];
        const uint4 B = rb[s * 17 + 1];
        const unsigned h[8] = {A.x, A.y, A.z, A.w, B.x, B.y, B.z, B.w};
        unsigned sft[7];
        #pragma unroll
        for (int m = 0; m < 7; ++m) sft[m] = __byte_perm(h[m], h[m + 1], 0x5432);

        // acc0 uses weight row s (s<7); acc1 uses weight row s-1 (s>0).
        // tap j even -> sft[j/2+p]; j odd -> h[(j+1)/2+p].
        #pragma unroll
        for (int q = 0; q < 4; ++q) {
            const uint4 w = wq[s * 4 + q];       // one broadcast LDS.128: 2 taps x 2 rows
            // j = 2q (even)
            #pragma unroll
            for (int p = 0; p < 4; ++p) {
                const __half2 tap = u2h(sft[q + p]);
                if (s < 7) acc0[p] = __hmax2(acc0[p], __hadd2(tap, u2h(w.x)));
                if (s > 0) acc1[p] = __hmax2(acc1[p], __hadd2(tap, u2h(w.y)));
            }
            // j = 2q+1 (odd), skip j==7
            if (q < 3) {
                #pragma unroll
                for (int p = 0; p < 4; ++p) {
                    const __half2 tap = u2h(h[q + 1 + p]);
                    if (s < 7) acc0[p] = __hmax2(acc0[p], __hadd2(tap, u2h(w.z)));
                    if (s > 0) acc1[p] = __hmax2(acc1[p], __hadd2(tap, u2h(w.w)));
                }
            }
        }
    }

    // ---- convert fp16 -> fp32, store 2x STG.128 per row ----
    float* go = out + (size_t)plane * (HH * WW);
    {
        float2 f0 = __half22float2(acc0[0]);
        float2 f1 = __half22float2(acc0[1]);
        float2 f2 = __half22float2(acc0[2]);
        float2 f3 = __half22float2(acc0[3]);
        float4* op = reinterpret_cast<float4*>(&go[(R0 + r0) * WW + cbase]);
        op[0] = make_float4(f0.x, f0.y, f1.x, f1.y);
        op[1] = make_float4(f2.x, f2.y, f3.x, f3.y);
    }
    {
        float2 f0 = __half22float2(acc1[0]);
        float2 f1 = __half22float2(acc1[1]);
        float2 f2 = __half22float2(acc1[2]);
        float2 f3 = __half22float2(acc1[3]);
        float4* op = reinterpret_cast<float4*>(&go[(R0 + r0 + 1) * WW + cbase]);
        op[0] = make_float4(f0.x, f0.y, f1.x, f1.y);
        op[1] = make_float4(f2.x, f2.y, f3.x, f3.y);
    }
}

extern "C" void kernel_launch(void* const* d_in, const int* in_sizes, int n_in,
                              void* d_out, int out_size) {
    const float* x  = (const float*)d_in[0];
    const float* wt = (const float*)d_in[1];
    float* out = (float*)d_out;
    morph7x7_h2_kernel<<<BB * CC * 4, NT>>>(x, wt, out);
}

// round 17
// speedup vs baseline: 1.0079x; 1.0079x over previous
#include <cuda_runtime.h>
#include <cuda_fp16.h>

// Morphological dilation2d, K=7, PAD=3 (zero padding = nn.Unfold), then ReLU.
// out[b,c,h,w] = max(0, max_{i,j}( xp[b,c,h+i,w+j] + weight[c,i,j] ))
// Packed fp16x2 (HADD2 + HMNMX2); ReLU folded into acc init (=0).
//
// Warp-autonomous version: NO __syncthreads. Warp w computes output rows
// 4w..4w+3 and fills its own 10 padded slab rows (out-of-range rows load as
// zeros), zeroes its own side halos, and builds a private weight table.
// Only a __syncwarp separates fill from compute -> no cross-warp convoy.
// Fill redundancy (2.1x) is absorbed by L2. Grid 6144, 7 CTAs/SM.
//
// x:      (16, 96, 128, 128) fp32 -> d_in[0]
// weight: (96, 7, 7)         fp32 -> d_in[1]
// out:    fp32

#define HH    128
#define WW    128
#define CC    96
#define BB    16
#define RPC   32            // output rows per CTA
#define SR    38            // smem rows = RPC + 6
#define SROWH 136           // smem row stride in HALVES (272B)
#define NT    256

__device__ __forceinline__ __half2 u2h(unsigned u) { return *reinterpret_cast<__half2*>(&u); }

__global__ __launch_bounds__(NT, 7)
void morph7x7_h2_kernel(const float* __restrict__ x,
                        const float* __restrict__ wt,
                        float* __restrict__ out) {
    __shared__ __half xs[SR * SROWH];
    __shared__ uint4  wqw[8 * 32];          // per-warp quad-paired weight tables

    const int bid   = blockIdx.x;
    const int rtile = bid & 3;
    const int plane = bid >> 2;             // b*CC + c
    const int c     = plane % CC;
    const int R0    = rtile * RPC;

    const float* gx = x + (size_t)plane * (HH * WW);
    const int tid  = threadIdx.x;
    const int lane = tid & 31;
    const int wid  = tid >> 5;              // warp 0..7, owns slab rows 4w..4w+9

    // ---- per-warp side halo: rows 4w..4w+9, half-cols 0-3 and 132-135 ----
    if (lane < 20) {
        const int row  = wid * 4 + (lane >> 1);
        const int side = lane & 1;
        // covers rows 4w .. 4w+9 via two strided passes
        *reinterpret_cast<uint2*>(&xs[row * SROWH + side * 132]) = make_uint2(0u, 0u);
        if ((lane >> 1) + 5 < 10) {
            const int row2 = wid * 4 + (lane >> 1) + 5;
            *reinterpret_cast<uint2*>(&xs[row2 * SROWH + side * 132]) = make_uint2(0u, 0u);
        }
    }

    // ---- per-warp quad-paired weight table ----
    // wqw[wid*32 + s*4+q] = (w2[s][2q], w2[s-1][2q], w2[s][2q+1], w2[s-1][2q+1])
    {
        const int s = lane >> 2, q = lane & 3;
        const int j0 = 2 * q, j1 = 2 * q + 1;
        unsigned e0 = 0u, e1 = 0u, e2 = 0u, e3 = 0u;
        if (s < 7) {
            __half2 h2 = __half2half2(__float2half_rn(wt[c * 49 + s * 7 + j0]));
            e0 = *reinterpret_cast<unsigned*>(&h2);
            if (j1 < 7) {
                __half2 g2 = __half2half2(__float2half_rn(wt[c * 49 + s * 7 + j1]));
                e2 = *reinterpret_cast<unsigned*>(&g2);
            }
        }
        if (s > 0) {
            __half2 h2 = __half2half2(__float2half_rn(wt[c * 49 + (s - 1) * 7 + j0]));
            e1 = *reinterpret_cast<unsigned*>(&h2);
            if (j1 < 7) {
                __half2 g2 = __half2half2(__float2half_rn(wt[c * 49 + (s - 1) * 7 + j1]));
                e3 = *reinterpret_cast<unsigned*>(&g2);
            }
        }
        wqw[(wid << 5) + lane] = make_uint4(e0, e1, e2, e3);
    }

    // ---- per-warp fill: slab rows 4w..4w+9; out-of-range global rows -> zeros ----
    // lane = float4 column (0..31); data lands at half-col 4, 8B-aligned STS.64.
    #pragma unroll
    for (int i = 0; i < 10; ++i) {
        const int row = wid * 4 + i;            // slab row
        const int g   = R0 + row - 3;           // global row
        float4 v = make_float4(0.f, 0.f, 0.f, 0.f);
        if (g >= 0 && g < HH)
            v = reinterpret_cast<const float4*>(gx + g * WW)[lane];
        __half2 p0 = __floats2half2_rn(v.x, v.y);
        __half2 p1 = __floats2half2_rn(v.z, v.w);
        uint2 pk = make_uint2(*reinterpret_cast<unsigned*>(&p0),
                              *reinterpret_cast<unsigned*>(&p1));
        *reinterpret_cast<uint2*>(&xs[row * SROWH + 4 + lane * 4]) = pk;
    }
    __syncwarp();                               // the ONLY synchronization

    // ---- compute: thread = 8 cols x 2 rows (rows within this warp's region) ----
    const int tx    = tid & 15;
    const int ty    = tid >> 4;
    const int cbase = tx * 8;               // output col base; LDS.128-aligned reads
    const int r0    = ty * 2;               // in [4*wid, 4*wid+2]

    // S[0..3]=0 pad; taps for output col w are S[w+1 .. w+7].
    const uint4* rb = reinterpret_cast<const uint4*>(&xs[r0 * SROWH + cbase]);
    const uint4* wq = &wqw[wid << 5];

    __half2 acc0[4], acc1[4];
    const __half2 h2z = __float2half2_rn(0.0f);
    #pragma unroll
    for (int p = 0; p < 4; ++p) { acc0[p] = h2z; acc1[p] = h2z; }   // folds ReLU

    #pragma unroll
    for (int s = 0; s < 8; ++s) {
        const uint4 A = rb[s * 17];
        const uint4 B = rb[s * 17 + 1];
        const unsigned h[8] = {A.x, A.y, A.z, A.w, B.x, B.y, B.z, B.w};
        unsigned sft[7];
        #pragma unroll
        for (int m = 0; m < 7; ++m) sft[m] = __byte_perm(h[m], h[m + 1], 0x5432);

        // acc0 uses weight row s (s<7); acc1 uses weight row s-1 (s>0).
        // tap j even -> sft[j/2+p]; j odd -> h[(j+1)/2+p].
        #pragma unroll
        for (int q = 0; q < 4; ++q) {
            const uint4 w = wq[s * 4 + q];       // broadcast LDS.128: 2 taps x 2 rows
            // j = 2q (even)
            #pragma unroll
            for (int p = 0; p < 4; ++p) {
                const __half2 tap = u2h(sft[q + p]);
                if (s < 7) acc0[p] = __hmax2(acc0[p], __hadd2(tap, u2h(w.x)));
                if (s > 0) acc1[p] = __hmax2(acc1[p], __hadd2(tap, u2h(w.y)));
            }
            // j = 2q+1 (odd), skip j==7
            if (q < 3) {
                #pragma unroll
                for (int p = 0; p < 4; ++p) {
                    const __half2 tap = u2h(h[q + 1 + p]);
                    if (s < 7) acc0[p] = __hmax2(acc0[p], __hadd2(tap, u2h(w.z)));
                    if (s > 0) acc1[p] = __hmax2(acc1[p], __hadd2(tap, u2h(w.w)));
                }
            }
        }
    }

    // ---- convert fp16 -> fp32, store 2x STG.128 per row ----
    float* go = out + (size_t)plane * (HH * WW);
    {
        float2 f0 = __half22float2(acc0[0]);
        float2 f1 = __half22float2(acc0[1]);
        float2 f2 = __half22float2(acc0[2]);
        float2 f3 = __half22float2(acc0[3]);
        float4* op = reinterpret_cast<float4*>(&go[(R0 + r0) * WW + cbase]);
        op[0] = make_float4(f0.x, f0.y, f1.x, f1.y);
        op[1] = make_float4(f2.x, f2.y, f3.x, f3.y);
    }
    {
        float2 f0 = __half22float2(acc1[0]);
        float2 f1 = __half22float2(acc1[1]);
        float2 f2 = __half22float2(acc1[2]);
        float2 f3 = __half22float2(acc1[3]);
        float4* op = reinterpret_cast<float4*>(&go[(R0 + r0 + 1) * WW + cbase]);
        op[0] = make_float4(f0.x, f0.y, f1.x, f1.y);
        op[1] = make_float4(f2.x, f2.y, f3.x, f3.y);
    }
}

extern "C" void kernel_launch(void* const* d_in, const int* in_sizes, int n_in,
                              void* d_out, int out_size) {
    const float* x  = (const float*)d_in[0];
    const float* wt = (const float*)d_in[1];
    float* out = (float*)d_out;
    morph7x7_h2_kernel<<<BB * CC * 4, NT>>>(x, wt, out);
}